// round 2
// baseline (speedup 1.0000x reference)
#include <cuda_runtime.h>
#include <math.h>

#define N_NODES 50000
#define N_EDGES 300000
#define DIM 256
#define N_RELS 500

// Scratch (device globals — no allocations allowed in kernel_launch)
__device__ float g_pre [N_NODES * DIM];   // segment_sum(h[src]+emb[etype]) per dst
__device__ float g_agg [N_NODES * DIM];   // pre @ Wn
__device__ float g_loop[N_NODES * DIM];   // h @ loop_weight (fixed up for indeg==0)
__device__ float g_skip[N_NODES * DIM];   // prev_h @ skip_w (pre-sigmoid, pre-bias)
__device__ int   g_indeg[N_NODES];

// ---------------------------------------------------------------------------
// 1) zero scratch
// ---------------------------------------------------------------------------
__global__ void zero_kernel() {
    int i = blockIdx.x * blockDim.x + threadIdx.x;
    const int total4 = N_NODES * DIM / 4;
    float4 z = make_float4(0.f, 0.f, 0.f, 0.f);
    for (int idx = i; idx < total4; idx += gridDim.x * blockDim.x)
        reinterpret_cast<float4*>(g_pre)[idx] = z;
    if (i < N_NODES) g_indeg[i] = 0;
}

// ---------------------------------------------------------------------------
// 2) edge scatter: pre[dst] += h[src] + emb_rel[etype];  indeg[dst] += 1
//    64 threads per edge (each a float4 = 16B); indices warp-uniform ->
//    broadcast index loads. Vector RED quarters the LTS atomic op count.
// ---------------------------------------------------------------------------
__global__ void edge_kernel(const float* __restrict__ h,
                            const float* __restrict__ emb,
                            const int*   __restrict__ src,
                            const int*   __restrict__ dst,
                            const int*   __restrict__ etype) {
    long long tid = (long long)blockIdx.x * blockDim.x + threadIdx.x;
    int e = (int)(tid >> 6);           // 64 float4 per edge
    int j = (int)(tid & 63);
    if (e >= N_EDGES) return;
    int s = src[e];
    int d = dst[e];
    int r = etype[e];
    if (j == 0) atomicAdd(&g_indeg[d], 1);

    float4 hv = reinterpret_cast<const float4*>(h   + (size_t)s * DIM)[j];
    float4 ev = reinterpret_cast<const float4*>(emb + (size_t)r * DIM)[j];
    float4 v = make_float4(hv.x + ev.x, hv.y + ev.y, hv.z + ev.z, hv.w + ev.w);

    float* p = g_pre + (size_t)d * DIM + (size_t)j * 4;
    asm volatile("red.global.add.v4.f32 [%0], {%1, %2, %3, %4};"
                 :: "l"(p), "f"(v.x), "f"(v.y), "f"(v.z), "f"(v.w)
                 : "memory");
}

// ---------------------------------------------------------------------------
// 3) three fused-shape SGEMMs: C = A @ B, M=50000, N=K=256
//    blockIdx.z selects (A,B,C) — device globals referenced DEVICE-SIDE ONLY
//    (passing a __device__ symbol from host binds the host shadow array,
//    which GB300's ATS happily dereferences as zeros — the R1 bug).
//    128x128 tile, BK=16, 8x8/thread (split 4+4 for conflict-free LDS.128).
// ---------------------------------------------------------------------------
__global__ __launch_bounds__(256)
void gemm3_kernel(const float* __restrict__ A_h,
                  const float* __restrict__ A_prev,
                  const float* __restrict__ B_wn,
                  const float* __restrict__ B_loop,
                  const float* __restrict__ B_skip) {
    const float* A; const float* B; float* C;
    if      (blockIdx.z == 0) { A = g_pre;  B = B_wn;   C = g_agg;  }
    else if (blockIdx.z == 1) { A = A_h;    B = B_loop; C = g_loop; }
    else                      { A = A_prev; B = B_skip; C = g_skip; }

    const int M = N_NODES, K = DIM, N = DIM;
    __shared__ float As[16][128];   // A^T tile
    __shared__ float Bs[16][128];

    const int tid  = threadIdx.x;
    const int row0 = blockIdx.x * 128;
    const int col0 = blockIdx.y * 128;
    const int tx = tid & 15;        // 16 thread-cols
    const int ty = tid >> 4;        // 16 thread-rows

    // global load mapping
    const int arow = tid >> 2;            // 0..63
    const int acol = (tid & 3) * 4;       // 0,4,8,12
    const int brow = tid >> 5;            // 0..7
    const int bcol = (tid & 31) * 4;      // 0..124

    float acc[8][8];
    #pragma unroll
    for (int i = 0; i < 8; i++)
        #pragma unroll
        for (int j = 0; j < 8; j++) acc[i][j] = 0.f;

    for (int k0 = 0; k0 < K; k0 += 16) {
        #pragma unroll
        for (int i = 0; i < 2; i++) {
            int r = row0 + arow + i * 64;
            float4 v = (r < M)
                ? *reinterpret_cast<const float4*>(A + (size_t)r * K + k0 + acol)
                : make_float4(0.f, 0.f, 0.f, 0.f);
            As[acol + 0][arow + i * 64] = v.x;
            As[acol + 1][arow + i * 64] = v.y;
            As[acol + 2][arow + i * 64] = v.z;
            As[acol + 3][arow + i * 64] = v.w;
        }
        #pragma unroll
        for (int i = 0; i < 2; i++) {
            int r = k0 + brow + i * 8;
            *reinterpret_cast<float4*>(&Bs[brow + i * 8][bcol]) =
                *reinterpret_cast<const float4*>(B + (size_t)r * N + col0 + bcol);
        }
        __syncthreads();

        #pragma unroll
        for (int k = 0; k < 16; k++) {
            float4 a0 = *reinterpret_cast<const float4*>(&As[k][ty * 4]);
            float4 a1 = *reinterpret_cast<const float4*>(&As[k][64 + ty * 4]);
            float4 b0 = *reinterpret_cast<const float4*>(&Bs[k][tx * 4]);
            float4 b1 = *reinterpret_cast<const float4*>(&Bs[k][64 + tx * 4]);
            float ra[8] = {a0.x, a0.y, a0.z, a0.w, a1.x, a1.y, a1.z, a1.w};
            float rb[8] = {b0.x, b0.y, b0.z, b0.w, b1.x, b1.y, b1.z, b1.w};
            #pragma unroll
            for (int i = 0; i < 8; i++)
                #pragma unroll
                for (int j = 0; j < 8; j++)
                    acc[i][j] += ra[i] * rb[j];
        }
        __syncthreads();
    }

    // store: rows {row0 + ih*64 + ty*4 + i}, cols {col0 + jh*64 + tx*4 + j}
    #pragma unroll
    for (int ih = 0; ih < 2; ih++) {
        #pragma unroll
        for (int i = 0; i < 4; i++) {
            int r = row0 + ih * 64 + ty * 4 + i;
            if (r < M) {
                #pragma unroll
                for (int jh = 0; jh < 2; jh++) {
                    float4 v = make_float4(acc[ih * 4 + i][jh * 4 + 0],
                                           acc[ih * 4 + i][jh * 4 + 1],
                                           acc[ih * 4 + i][jh * 4 + 2],
                                           acc[ih * 4 + i][jh * 4 + 3]);
                    *reinterpret_cast<float4*>(C + (size_t)r * N + col0 + jh * 64 + tx * 4) = v;
                }
            }
        }
    }
}

// ---------------------------------------------------------------------------
// 4) fixup: rows with indeg==0 use evolve_loop_weight (~124 rows expected)
// ---------------------------------------------------------------------------
__global__ void fixup_kernel(const float* __restrict__ h,
                             const float* __restrict__ We) {
    int n = blockIdx.x;
    if (g_indeg[n] != 0) return;       // block-uniform branch
    __shared__ float hr[DIM];
    int t = threadIdx.x;               // 256 threads, one output col each
    hr[t] = h[(size_t)n * DIM + t];
    __syncthreads();
    float acc = 0.f;
    #pragma unroll 8
    for (int k = 0; k < DIM; k++)
        acc += hr[k] * We[(size_t)k * DIM + t];
    g_loop[(size_t)n * DIM + t] = acc;
}

// ---------------------------------------------------------------------------
// 5) fused epilogue: out = relu(sig(skip+b) * (agg*norm + loop) + (1-sig)*prev)
// ---------------------------------------------------------------------------
__global__ void final_kernel(const float* __restrict__ prevh,
                             const float* __restrict__ norm,
                             const float* __restrict__ bias,
                             float* __restrict__ out) {
    int i4 = blockIdx.x * blockDim.x + threadIdx.x;
    const int total4 = N_NODES * DIM / 4;
    if (i4 >= total4) return;
    int n  = i4 >> 6;            // DIM/4 = 64 float4 per row
    int d4 = i4 & 63;

    float  nm = norm[n];
    float4 sk = reinterpret_cast<const float4*>(g_skip)[i4];
    float4 ag = reinterpret_cast<const float4*>(g_agg)[i4];
    float4 lp = reinterpret_cast<const float4*>(g_loop)[i4];
    float4 pv = reinterpret_cast<const float4*>(prevh)[i4];
    float4 bs = reinterpret_cast<const float4*>(bias)[d4];

    float r[4];
    float skv[4] = {sk.x + bs.x, sk.y + bs.y, sk.z + bs.z, sk.w + bs.w};
    float agv[4] = {ag.x, ag.y, ag.z, ag.w};
    float lpv[4] = {lp.x, lp.y, lp.z, lp.w};
    float pvv[4] = {pv.x, pv.y, pv.z, pv.w};
    #pragma unroll
    for (int c = 0; c < 4; c++) {
        float s = 1.f / (1.f + __expf(-skv[c]));
        float v = s * (agv[c] * nm + lpv[c]) + (1.f - s) * pvv[c];
        r[c] = fmaxf(v, 0.f);
    }
    reinterpret_cast<float4*>(out)[i4] = make_float4(r[0], r[1], r[2], r[3]);
}

// ---------------------------------------------------------------------------
extern "C" void kernel_launch(void* const* d_in, const int* in_sizes, int n_in,
                              void* d_out, int out_size) {
    const float* h       = (const float*)d_in[0];
    const float* prev_h  = (const float*)d_in[1];
    const float* emb_rel = (const float*)d_in[2];
    const float* norm    = (const float*)d_in[3];
    const float* w_n     = (const float*)d_in[4];
    const float* w_loop  = (const float*)d_in[5];
    const float* w_ev    = (const float*)d_in[6];
    const float* w_skip  = (const float*)d_in[7];
    const float* b_skip  = (const float*)d_in[8];
    const int*   src     = (const int*)d_in[9];
    const int*   dst     = (const int*)d_in[10];
    const int*   etype   = (const int*)d_in[11];
    float* out = (float*)d_out;

    // 1) zero scratch
    zero_kernel<<<2048, 256>>>();

    // 2) edge scatter (300000 edges * 64 float4)
    {
        long long threads = (long long)N_EDGES * 64;
        int blocks = (int)((threads + 255) / 256);
        edge_kernel<<<blocks, 256>>>(h, emb_rel, src, dst, etype);
    }

    // 3) the three GEMMs (device-global operands resolved inside the kernel)
    {
        dim3 grid((N_NODES + 127) / 128, DIM / 128, 3);
        gemm3_kernel<<<grid, 256>>>(h, prev_h, w_n, w_loop, w_skip);
    }

    // 4) evolve fixup for indeg==0 rows
    fixup_kernel<<<N_NODES, DIM>>>(h, w_ev);

    // 5) fused epilogue
    {
        int total4 = N_NODES * DIM / 4;
        final_kernel<<<(total4 + 255) / 256, 256>>>(prev_h, norm, b_skip, out);
    }
}